// round 14
// baseline (speedup 1.0000x reference)
#include <cuda_runtime.h>
#include <cuda_bf16.h>
#include <cstdint>

// Dequant: out[r][c] = (float)q[r][c] * row_stats[r] * (1/127)
// ROWS = COLS = 8192, int32 in -> fp32 out. Pure streaming: 512 MiB total.
//
// R14: final sweep axis — block size. Same measured-best hot path as
// R3/R6/R8 (front-batched MLP=8 LDG.E.128, .cs both directions, uniform
// per-block scale) but TPB=128: one block == HALF a row (128 thr x 8 int4
// = 1024 vecs = 4096 cols), grid 16384. Doubles the number of independent
// schedulable units -> finer work-steal granularity, smoother last-wave
// drain. Scale stays uniform: row = blockIdx.x >> 1 (one shift per block).
// Prior sweep (kernel us): VPT x1/x4/x8 = 82.5/74.5/73.9; stores
// .cs/.wt/default = 73.9/75.3/75.5; strided/contig = 73.9/75.2;
// oversub/persistent = 73.9/78.9; 256b LDG = 75.2. All at 80-82%
// DRAM-active = B300 mixed 1:1 r/w HBM ceiling.

#define VPT 8                         // int4 vectors per thread
#define TPB 128                       // TPB*VPT = 1024 vecs = half a row

__global__ void __launch_bounds__(TPB, 12)
dequant_kernel(const int4* __restrict__ q,
               const float* __restrict__ row_stats,
               float4* __restrict__ out)
{
    // Two blocks per row: uniform per-block scale.
    const float scale = __ldg(&row_stats[blockIdx.x >> 1]) * (1.0f / 127.0f);

    const int base = blockIdx.x * (TPB * VPT) + threadIdx.x;

    // Front-batch 8 independent LDG.E.128 (MLP=8), streaming hint.
    int4 v[VPT];
#pragma unroll
    for (int j = 0; j < VPT; j++)
        v[j] = __ldcs(&q[base + j * TPB]);

#pragma unroll
    for (int j = 0; j < VPT; j++) {
        float4 r;
        r.x = (float)v[j].x * scale;
        r.y = (float)v[j].y * scale;
        r.z = (float)v[j].z * scale;
        r.w = (float)v[j].w * scale;
        __stcs(&out[base + j * TPB], r);   // streaming store (measured best)
    }
}

extern "C" void kernel_launch(void* const* d_in, const int* in_sizes, int n_in,
                              void* d_out, int out_size)
{
    const int4*  q         = (const int4*)d_in[0];   // int32 [8192,8192]
    const float* row_stats = (const float*)d_in[1];  // fp32  [8192]
    float4*      out       = (float4*)d_out;

    const int rows = in_sizes[1];                    // 8192
    const int blocks = rows * 2;                     // 16384, half-row blocks

    dequant_kernel<<<blocks, TPB>>>(q, row_stats, out);
}